// round 1
// baseline (speedup 1.0000x reference)
#include <cuda_runtime.h>
#include <math.h>

// ---------------------------------------------------------------------------
// Problem shape (fixed by the dataset): B=2, S=4096, H=1024, I=3072
// ---------------------------------------------------------------------------
#define M_TOK 8192        // B*S
#define H_DIM 1024
#define I_DIM 3072

// ---------------------------------------------------------------------------
// Scratch (static __device__ arrays: allocation-free per harness rules)
// ---------------------------------------------------------------------------
__device__ float g_xq  [(size_t)M_TOK * H_DIM];          //  33.5 MB quantized x
__device__ float g_wu  [(size_t)I_DIM * H_DIM];          //  12.6 MB dequant w_up
__device__ float g_wg  [(size_t)I_DIM * H_DIM];          //  12.6 MB dequant w_gate
__device__ float g_wd  [(size_t)H_DIM * I_DIM];          //  12.6 MB dequant w_down
__device__ float g_up  [(size_t)M_TOK * I_DIM];          // 100.7 MB up_raw -> p
__device__ float g_gate[(size_t)M_TOK * I_DIM];          // 100.7 MB gate_raw -> t
__device__ unsigned int g_amax[8];                        // bit patterns of |max|
// slots: 0=x  1=up_raw  2=gate_raw  3=t(gate1*sig)  4=p(gate2*up)

// ---------------------------------------------------------------------------
// Helpers
// ---------------------------------------------------------------------------
__device__ __forceinline__ float qdq16(float v, float scale) {
    // act_qdq with precomputed scale: clip(round(v/scale), -32768, 32767)*scale
    float q = rintf(__fdiv_rn(v, scale));
    q = fminf(fmaxf(q, -32768.0f), 32767.0f);
    return q * scale;
}
__device__ __forceinline__ float scale16(float amax) {
    return fmaxf(__fdiv_rn(amax, 32767.0f), 1e-12f);
}

__global__ void k_zero_amax() {
    if (threadIdx.x < 8) g_amax[threadIdx.x] = 0u;
}

// per-tensor absmax over float4 view
__global__ void k_amax(const float4* __restrict__ p, size_t n4, int slot) {
    float m = 0.0f;
    for (size_t i = (size_t)blockIdx.x * blockDim.x + threadIdx.x; i < n4;
         i += (size_t)gridDim.x * blockDim.x) {
        float4 v = p[i];
        m = fmaxf(m, fmaxf(fmaxf(fabsf(v.x), fabsf(v.y)),
                           fmaxf(fabsf(v.z), fabsf(v.w))));
    }
    #pragma unroll
    for (int o = 16; o; o >>= 1) m = fmaxf(m, __shfl_xor_sync(0xffffffffu, m, o));
    __shared__ float red[32];
    int wid = threadIdx.x >> 5, lid = threadIdx.x & 31;
    if (lid == 0) red[wid] = m;
    __syncthreads();
    if (threadIdx.x == 0) {
        int nw = (blockDim.x + 31) >> 5;
        float mm = red[0];
        for (int i = 1; i < nw; i++) mm = fmaxf(mm, red[i]);
        atomicMax(&g_amax[slot], __float_as_uint(mm));
    }
}

// out[i] = qdq16(in[i], scale_from_slot)   (in==out allowed)
__global__ void k_quant(const float4* __restrict__ in, float4* __restrict__ out,
                        size_t n4, int slot) {
    float s = scale16(__uint_as_float(g_amax[slot]));
    for (size_t i = (size_t)blockIdx.x * blockDim.x + threadIdx.x; i < n4;
         i += (size_t)gridDim.x * blockDim.x) {
        float4 v = in[i];
        v.x = qdq16(v.x, s); v.y = qdq16(v.y, s);
        v.z = qdq16(v.z, s); v.w = qdq16(v.w, s);
        out[i] = v;
    }
}

// blockwise 4-bit weight fake quant-dequant. One warp handles one 32-block.
__global__ void k_dequant_w(const float* __restrict__ w, float* __restrict__ o,
                            int nblocks) {
    int warp = (blockIdx.x * blockDim.x + threadIdx.x) >> 5;
    int lane = threadIdx.x & 31;
    if (warp >= nblocks) return;
    size_t base = (size_t)warp * 32;
    float v = w[base + lane];
    float a = fabsf(v);
    #pragma unroll
    for (int off = 16; off; off >>= 1) a = fmaxf(a, __shfl_xor_sync(0xffffffffu, a, off));
    float s = fmaxf(__fdiv_rn(a, 7.0f), 1e-12f);
    float q = rintf(__fdiv_rn(v, s));
    q = fminf(fmaxf(q, -8.0f), 7.0f);
    o[base + lane] = q * s;
}

// gate1 = qdq(gate_raw); sig = fixed_u16(sigmoid(gate1)); t = gate1*sig
// in-place on g_gate; accumulates amax(t) into slot 3
__global__ void k_silu(float4* __restrict__ gate, size_t n4) {
    float sg = scale16(__uint_as_float(g_amax[2]));
    float m = 0.0f;
    for (size_t i = (size_t)blockIdx.x * blockDim.x + threadIdx.x; i < n4;
         i += (size_t)gridDim.x * blockDim.x) {
        float4 v = gate[i];
        float r[4] = {v.x, v.y, v.z, v.w};
        #pragma unroll
        for (int c = 0; c < 4; c++) {
            float g1 = qdq16(r[c], sg);
            float sig = __fdiv_rn(1.0f, 1.0f + expf(-g1));
            sig = fminf(fmaxf(rintf(sig * 65536.0f), 0.0f), 65535.0f) * (1.0f / 65536.0f);
            float t = g1 * sig;
            r[c] = t;
            m = fmaxf(m, fabsf(t));
        }
        gate[i] = make_float4(r[0], r[1], r[2], r[3]);
    }
    #pragma unroll
    for (int o = 16; o; o >>= 1) m = fmaxf(m, __shfl_xor_sync(0xffffffffu, m, o));
    __shared__ float red[32];
    int wid = threadIdx.x >> 5, lid = threadIdx.x & 31;
    if (lid == 0) red[wid] = m;
    __syncthreads();
    if (threadIdx.x == 0) {
        int nw = (blockDim.x + 31) >> 5;
        float mm = red[0];
        for (int i = 1; i < nw; i++) mm = fmaxf(mm, red[i]);
        atomicMax(&g_amax[3], __float_as_uint(mm));
    }
}

// p = qdq(t, amax_t) * qdq(up_raw, amax_up); in-place on g_up; amax(p) -> slot 4
__global__ void k_mul(const float4* __restrict__ t, float4* __restrict__ up, size_t n4) {
    float st = scale16(__uint_as_float(g_amax[3]));
    float su = scale16(__uint_as_float(g_amax[1]));
    float m = 0.0f;
    for (size_t i = (size_t)blockIdx.x * blockDim.x + threadIdx.x; i < n4;
         i += (size_t)gridDim.x * blockDim.x) {
        float4 tv = t[i];
        float4 uv = up[i];
        float rt[4] = {tv.x, tv.y, tv.z, tv.w};
        float ru[4] = {uv.x, uv.y, uv.z, uv.w};
        #pragma unroll
        for (int c = 0; c < 4; c++) {
            float g2 = qdq16(rt[c], st);
            float u  = qdq16(ru[c], su);
            float p  = g2 * u;
            ru[c] = p;
            m = fmaxf(m, fabsf(p));
        }
        up[i] = make_float4(ru[0], ru[1], ru[2], ru[3]);
    }
    #pragma unroll
    for (int o = 16; o; o >>= 1) m = fmaxf(m, __shfl_xor_sync(0xffffffffu, m, o));
    __shared__ float red[32];
    int wid = threadIdx.x >> 5, lid = threadIdx.x & 31;
    if (lid == 0) red[wid] = m;
    __syncthreads();
    if (threadIdx.x == 0) {
        int nw = (blockDim.x + 31) >> 5;
        float mm = red[0];
        for (int i = 1; i < nw; i++) mm = fmaxf(mm, red[i]);
        atomicMax(&g_amax[4], __float_as_uint(mm));
    }
}

// ---------------------------------------------------------------------------
// SGEMM: C[M,N] = A[M,K] @ B[N,K]^T, optional fused per-tensor |max| epilogue
// 128x128x16 tile, 256 threads, 8x8 per-thread micro-tile.
// ---------------------------------------------------------------------------
#define BM 128
#define BN 128
#define BK 16

__global__ void __launch_bounds__(256, 2)
sgemm_tn(const float* __restrict__ A, const float* __restrict__ B,
         float* __restrict__ C, int M, int N, int K, unsigned int* amax_slot)
{
    __shared__ float As[BK][BM + 4];
    __shared__ float Bs[BK][BN + 4];

    const int tid = threadIdx.x;
    const int tx = tid & 15;   // n direction
    const int ty = tid >> 4;   // m direction
    const int m0 = blockIdx.y * BM;
    const int n0 = blockIdx.x * BN;

    const float* Ab = A + (size_t)m0 * K;
    const float* Bb = B + (size_t)n0 * K;

    float acc[8][8];
    #pragma unroll
    for (int i = 0; i < 8; i++)
        #pragma unroll
        for (int j = 0; j < 8; j++) acc[i][j] = 0.0f;

    for (int k0 = 0; k0 < K; k0 += BK) {
        #pragma unroll
        for (int it = 0; it < 2; it++) {
            int idx = tid + it * 256;       // 0..511 (float4 units)
            int row = idx >> 2;             // 0..127
            int c4  = idx & 3;              // 0..3
            float4 va = *(const float4*)(Ab + (size_t)row * K + k0 + c4 * 4);
            As[c4 * 4 + 0][row] = va.x;
            As[c4 * 4 + 1][row] = va.y;
            As[c4 * 4 + 2][row] = va.z;
            As[c4 * 4 + 3][row] = va.w;
            float4 vb = *(const float4*)(Bb + (size_t)row * K + k0 + c4 * 4);
            Bs[c4 * 4 + 0][row] = vb.x;
            Bs[c4 * 4 + 1][row] = vb.y;
            Bs[c4 * 4 + 2][row] = vb.z;
            Bs[c4 * 4 + 3][row] = vb.w;
        }
        __syncthreads();
        #pragma unroll
        for (int k = 0; k < BK; k++) {
            float a[8], b[8];
            float4 a0 = *(const float4*)&As[k][ty * 8];
            float4 a1 = *(const float4*)&As[k][ty * 8 + 4];
            float4 b0 = *(const float4*)&Bs[k][tx * 8];
            float4 b1 = *(const float4*)&Bs[k][tx * 8 + 4];
            a[0]=a0.x; a[1]=a0.y; a[2]=a0.z; a[3]=a0.w;
            a[4]=a1.x; a[5]=a1.y; a[6]=a1.z; a[7]=a1.w;
            b[0]=b0.x; b[1]=b0.y; b[2]=b0.z; b[3]=b0.w;
            b[4]=b1.x; b[5]=b1.y; b[6]=b1.z; b[7]=b1.w;
            #pragma unroll
            for (int i = 0; i < 8; i++)
                #pragma unroll
                for (int j = 0; j < 8; j++)
                    acc[i][j] = fmaf(a[i], b[j], acc[i][j]);
        }
        __syncthreads();
    }

    float lmax = 0.0f;
    #pragma unroll
    for (int i = 0; i < 8; i++) {
        float* Crow = C + (size_t)(m0 + ty * 8 + i) * N + n0 + tx * 8;
        *(float4*)(Crow)     = make_float4(acc[i][0], acc[i][1], acc[i][2], acc[i][3]);
        *(float4*)(Crow + 4) = make_float4(acc[i][4], acc[i][5], acc[i][6], acc[i][7]);
        #pragma unroll
        for (int j = 0; j < 8; j++) lmax = fmaxf(lmax, fabsf(acc[i][j]));
    }

    if (amax_slot) {
        #pragma unroll
        for (int o = 16; o; o >>= 1)
            lmax = fmaxf(lmax, __shfl_xor_sync(0xffffffffu, lmax, o));
        __shared__ float red[8];
        if ((tid & 31) == 0) red[tid >> 5] = lmax;
        __syncthreads();
        if (tid == 0) {
            float m = red[0];
            #pragma unroll
            for (int i = 1; i < 8; i++) m = fmaxf(m, red[i]);
            atomicMax(amax_slot, __float_as_uint(m));
        }
    }
}

// ---------------------------------------------------------------------------
// Host launch
// ---------------------------------------------------------------------------
extern "C" void kernel_launch(void* const* d_in, const int* in_sizes, int n_in,
                              void* d_out, int out_size)
{
    const float* x  = (const float*)d_in[0];   // [2,4096,1024]
    const float* wg = (const float*)d_in[1];   // [3072,1024]
    const float* wu = (const float*)d_in[2];   // [3072,1024]
    const float* wd = (const float*)d_in[3];   // [1024,3072]
    float* out = (float*)d_out;                // [2,4096,1024]

    float *p_xq, *p_wu, *p_wg, *p_wd, *p_up, *p_gate;
    unsigned int* p_amax;
    cudaGetSymbolAddress((void**)&p_xq,   g_xq);
    cudaGetSymbolAddress((void**)&p_wu,   g_wu);
    cudaGetSymbolAddress((void**)&p_wg,   g_wg);
    cudaGetSymbolAddress((void**)&p_wd,   g_wd);
    cudaGetSymbolAddress((void**)&p_up,   g_up);
    cudaGetSymbolAddress((void**)&p_gate, g_gate);
    cudaGetSymbolAddress((void**)&p_amax, g_amax);

    const size_t nx  = (size_t)M_TOK * H_DIM;        // 8.39M
    const size_t ni  = (size_t)M_TOK * I_DIM;        // 25.2M
    const size_t nx4 = nx / 4;
    const size_t ni4 = ni / 4;

    k_zero_amax<<<1, 8>>>();

    // 1) per-tensor amax(x), then quantize x
    k_amax<<<2048, 256>>>((const float4*)x, nx4, 0);
    k_quant<<<2048, 256>>>((const float4*)x, (float4*)p_xq, nx4, 0);

    // 2) blockwise 4-bit weight dequant (3 weights)
    {
        int nb = (I_DIM * H_DIM) / 32;           // 98304 blocks per weight
        int cta = (nb * 32 + 255) / 256;
        k_dequant_w<<<cta, 256>>>(wu, p_wu, nb);
        k_dequant_w<<<cta, 256>>>(wg, p_wg, nb);
        k_dequant_w<<<cta, 256>>>(wd, p_wd, nb);
    }

    // 3) up_raw = xq @ w_up^T ; gate_raw = xq @ w_gate^T (fused amax epilogue)
    {
        dim3 grid(I_DIM / BN, M_TOK / BM);       // (24, 64)
        sgemm_tn<<<grid, 256>>>(p_xq, p_wu, p_up,   M_TOK, I_DIM, H_DIM, p_amax + 1);
        sgemm_tn<<<grid, 256>>>(p_xq, p_wg, p_gate, M_TOK, I_DIM, H_DIM, p_amax + 2);
    }

    // 4) t = qdq(gate)*fixed_u16(sigmoid(qdq(gate)))  (amax->3)
    k_silu<<<4096, 256>>>((float4*)p_gate, ni4);

    // 5) p = qdq(t)*qdq(up)  (amax->4), then o = qdq(p)
    k_mul<<<4096, 256>>>((const float4*)p_gate, (float4*)p_up, ni4);
    k_quant<<<4096, 256>>>((const float4*)p_up, (float4*)p_up, ni4, 4);

    // 6) out = o @ w_down^T
    {
        dim3 grid(H_DIM / BN, M_TOK / BM);       // (8, 64)
        sgemm_tn<<<grid, 256>>>(p_up, p_wd, out, M_TOK, H_DIM, I_DIM, nullptr);
    }
}

// round 3
// speedup vs baseline: 4.8725x; 4.8725x over previous
#include <cuda_runtime.h>
#include <cuda_bf16.h>
#include <math.h>
#include <stdint.h>

// ---------------------------------------------------------------------------
// Problem shape (fixed): B=2, S=4096, H=1024, I=3072
// ---------------------------------------------------------------------------
#define M_TOK 8192
#define H_DIM 1024
#define I_DIM 3072

#if defined(__CUDA_ARCH__) && defined(__CUDA_ARCH_FEAT_SM103_ALL)
#define HAVE_TCGEN05 1
#else
#define HAVE_TCGEN05 0
#endif

// ---------------------------------------------------------------------------
// Scratch (static __device__ arrays)
// ---------------------------------------------------------------------------
__device__ __nv_bfloat16 g_xh [(size_t)M_TOK * H_DIM];
__device__ __nv_bfloat16 g_xl [(size_t)M_TOK * H_DIM];
__device__ __nv_bfloat16 g_wuh[(size_t)I_DIM * H_DIM];
__device__ __nv_bfloat16 g_wul[(size_t)I_DIM * H_DIM];
__device__ __nv_bfloat16 g_wgh[(size_t)I_DIM * H_DIM];
__device__ __nv_bfloat16 g_wgl[(size_t)I_DIM * H_DIM];
__device__ __nv_bfloat16 g_wdh[(size_t)H_DIM * I_DIM];
__device__ __nv_bfloat16 g_wdl[(size_t)H_DIM * I_DIM];
__device__ float g_up  [(size_t)M_TOK * I_DIM];
__device__ float g_gate[(size_t)M_TOK * I_DIM];
__device__ __nv_bfloat16 g_ph [(size_t)M_TOK * I_DIM];
__device__ __nv_bfloat16 g_pl [(size_t)M_TOK * I_DIM];
__device__ unsigned int g_amax[8];
// slots: 0=x  1=up_raw  2=gate_raw  3=t  4=p

// ---------------------------------------------------------------------------
// Helpers
// ---------------------------------------------------------------------------
__device__ __forceinline__ float qdq16(float v, float scale) {
    float q = rintf(__fdiv_rn(v, scale));
    q = fminf(fmaxf(q, -32768.0f), 32767.0f);
    return q * scale;
}
__device__ __forceinline__ float scale16(float amax) {
    return fmaxf(__fdiv_rn(amax, 32767.0f), 1e-12f);
}
__device__ __forceinline__ uint32_t smem_u32(const void* p) {
    uint32_t a;
    asm("{ .reg .u64 t; cvta.to.shared.u64 t, %1; cvt.u32.u64 %0, t; }"
        : "=r"(a) : "l"(p));
    return a;
}

__device__ __forceinline__ void cp16(uint32_t dst, const void* src) {
    asm volatile("cp.async.cg.shared.global [%0], [%1], 16;"
                 :: "r"(dst), "l"(src) : "memory");
}

// ---------------------------------------------------------------------------
// Shared GEMM config: C[M,N] = (Ah+Al)[M,K] @ (Bh+Bl)[N,K]^T   (ll dropped)
// 128x128 tile, K-chunk 64, SW128-swizzled smem, 3-stage cp.async pipeline
// ---------------------------------------------------------------------------
#define NSTAGES 3
#define TILE_BYTES 16384
#define STAGE_BYTES (4 * TILE_BYTES)
#define GEMM_DYN_SMEM (NSTAGES * STAGE_BYTES + 1024)

__device__ __forceinline__ void load_chunk(
    uint32_t sbase,
    const __nv_bfloat16* __restrict__ Ah, const __nv_bfloat16* __restrict__ Al,
    const __nv_bfloat16* __restrict__ Bh, const __nv_bfloat16* __restrict__ Bl,
    int m0, int n0, int K, int k0, int tid)
{
    #pragma unroll
    for (int u = tid; u < 1024; u += 256) {
        int r = u >> 3, cc = u & 7;
        uint32_t off = (uint32_t)(r * 128 + cc * 16);
        uint32_t sw = off ^ ((off >> 3) & 0x70);
        size_t arow = (size_t)(m0 + r) * K + k0 + cc * 8;
        size_t brow = (size_t)(n0 + r) * K + k0 + cc * 8;
        cp16(sbase + sw,                  Ah + arow);
        cp16(sbase + TILE_BYTES + sw,     Al + arow);
        cp16(sbase + 2 * TILE_BYTES + sw, Bh + brow);
        cp16(sbase + 3 * TILE_BYTES + sw, Bl + brow);
    }
}

#if HAVE_TCGEN05
// ===== tcgen05 path (only if the 'a' feature target is available) ==========
#define MBARRIER_INIT(addr, cnt) \
    asm volatile("mbarrier.init.shared.b64 [%0], %1;" :: "r"(addr), "r"(cnt) : "memory")
#define MBARRIER_WAIT_PARITY(mbar_smem_addr, phase_parity) do { \
    uint32_t _mbar = (uint32_t)(mbar_smem_addr); \
    uint32_t _parity = (uint32_t)(phase_parity); \
    uint32_t _done; \
    asm volatile( \
        "{\n\t.reg .pred p;\n\t" \
        "mbarrier.try_wait.parity.acquire.cta.shared::cta.b64 p, [%1], %2;\n\t" \
        "selp.b32 %0, 1, 0, p;\n\t}" \
        : "=r"(_done) : "r"(_mbar), "r"(_parity) : "memory"); \
    if (!_done) { \
        asm volatile( \
            "{\n\t.reg .pred P1;\n\t" \
            "WAIT_LOOP_%=:\n\t" \
            "mbarrier.try_wait.parity.acquire.cta.shared::cta.b64 P1, [%0], %1, 0x989680;\n\t" \
            "@P1 bra.uni WAIT_DONE_%=;\n\t" \
            "bra.uni WAIT_LOOP_%=;\n\t" \
            "WAIT_DONE_%=:\n\t}" \
            :: "r"(_mbar), "r"(_parity) : "memory"); \
    } \
} while(0)

__device__ __forceinline__ uint64_t make_desc(uint32_t a) {
    const uint64_t base = (2ull << 61) | (1ull << 46) | (64ull << 32) | (1ull << 16);
    return base | ((uint64_t)(a >> 4) & 0x3FFFull);
}
__device__ __forceinline__ uint32_t elect_one() {
    uint32_t pred;
    asm volatile(
        "{\n\t.reg .pred p;\n\telect.sync _|p, 0xFFFFFFFF;\n\t"
        "selp.b32 %0, 1, 0, p;\n\t}"
        : "=r"(pred));
    return pred;
}
__device__ __forceinline__ void mma_f16_ss(uint32_t d, uint64_t ad, uint64_t bd,
                                           uint32_t idesc, uint32_t en) {
    asm volatile(
        "{\n\t.reg .pred p;\n\tsetp.ne.u32 p, %5, 0;\n\t"
        "tcgen05.mma.cta_group::1.kind::f16 [%0], %1, %2, %3, {%4, %4, %4, %4}, p;\n\t}"
        :: "r"(d), "l"(ad), "l"(bd), "r"(idesc), "r"(0u), "r"(en)
        : "memory");
}
#define TCGEN05_LD_X32(r, addr) \
    asm volatile( \
        "tcgen05.ld.sync.aligned.32x32b.x32.b32 " \
        "{%0, %1, %2, %3, %4, %5, %6, %7, " \
        " %8, %9, %10, %11, %12, %13, %14, %15, " \
        " %16, %17, %18, %19, %20, %21, %22, %23, " \
        " %24, %25, %26, %27, %28, %29, %30, %31}, [%32];" \
        : "=r"((r)[0]),  "=r"((r)[1]),  "=r"((r)[2]),  "=r"((r)[3]), \
          "=r"((r)[4]),  "=r"((r)[5]),  "=r"((r)[6]),  "=r"((r)[7]), \
          "=r"((r)[8]),  "=r"((r)[9]),  "=r"((r)[10]), "=r"((r)[11]), \
          "=r"((r)[12]), "=r"((r)[13]), "=r"((r)[14]), "=r"((r)[15]), \
          "=r"((r)[16]), "=r"((r)[17]), "=r"((r)[18]), "=r"((r)[19]), \
          "=r"((r)[20]), "=r"((r)[21]), "=r"((r)[22]), "=r"((r)[23]), \
          "=r"((r)[24]), "=r"((r)[25]), "=r"((r)[26]), "=r"((r)[27]), \
          "=r"((r)[28]), "=r"((r)[29]), "=r"((r)[30]), "=r"((r)[31]) \
        : "r"(addr))
#define IDESC_128 0x08200490u
#endif  // HAVE_TCGEN05

#if !HAVE_TCGEN05
// ===== mma.sync fallback helpers (base ISA) =================================
__device__ __forceinline__ void ldsm_x4(uint32_t addr, uint32_t* r) {
    asm volatile("ldmatrix.sync.aligned.m8n8.x4.shared.b16 {%0,%1,%2,%3}, [%4];"
                 : "=r"(r[0]), "=r"(r[1]), "=r"(r[2]), "=r"(r[3]) : "r"(addr));
}
__device__ __forceinline__ void mma16816(float* c, const uint32_t* a,
                                         uint32_t b0, uint32_t b1) {
    asm volatile(
        "mma.sync.aligned.m16n8k16.row.col.f32.bf16.bf16.f32 "
        "{%0,%1,%2,%3}, {%4,%5,%6,%7}, {%8,%9}, {%0,%1,%2,%3};"
        : "+f"(c[0]), "+f"(c[1]), "+f"(c[2]), "+f"(c[3])
        : "r"(a[0]), "r"(a[1]), "r"(a[2]), "r"(a[3]), "r"(b0), "r"(b1));
}
#endif

// ---------------------------------------------------------------------------
// The GEMM kernel (dual body, one symbol)
// ---------------------------------------------------------------------------
__global__ void __launch_bounds__(256, 1)
gemm_bf16_split(const __nv_bfloat16* __restrict__ Ah, const __nv_bfloat16* __restrict__ Al,
                const __nv_bfloat16* __restrict__ Bh, const __nv_bfloat16* __restrict__ Bl,
                float* __restrict__ C, int N, int K, unsigned int* amax_slot)
{
    extern __shared__ char dynsmem[];
    __shared__ float s_red[8];
    const int tid = threadIdx.x;
    const int wid = tid >> 5;
    const int lid = tid & 31;
    const int m0 = blockIdx.y * 128;
    const int n0 = blockIdx.x * 128;
    const int NC = K >> 6;
    uint32_t dynbase = smem_u32(dynsmem);
    dynbase = (dynbase + 1023u) & ~1023u;

#if HAVE_TCGEN05
    __shared__ uint32_t s_tmem[1];
    __shared__ __align__(8) unsigned long long s_mbar[NSTAGES];
    if (wid == 0) {
        asm volatile("tcgen05.alloc.cta_group::1.sync.aligned.shared::cta.b32 [%0], %1;"
                     :: "r"(smem_u32(s_tmem)), "r"(128u) : "memory");
        asm volatile("tcgen05.relinquish_alloc_permit.cta_group::1.sync.aligned;");
    }
    if (tid == 0) {
        #pragma unroll
        for (int s = 0; s < NSTAGES; s++) MBARRIER_INIT(smem_u32(&s_mbar[s]), 1u);
    }
    __syncthreads();
    const uint32_t tb = s_tmem[0];

    #pragma unroll
    for (int c = 0; c < NSTAGES; c++) {
        load_chunk(dynbase + c * STAGE_BYTES, Ah, Al, Bh, Bl, m0, n0, K, c * 64, tid);
        asm volatile("cp.async.commit_group;" ::: "memory");
    }
    for (int c = 0; c < NC; ++c) {
        int s = c - (c / NSTAGES) * NSTAGES;
        asm volatile("cp.async.wait_group %0;" :: "n"(NSTAGES - 1) : "memory");
        __syncthreads();
        if (wid == 0 && elect_one()) {
            asm volatile("fence.proxy.async.shared::cta;" ::: "memory");
            uint32_t sb = dynbase + s * STAGE_BYTES;
            uint64_t dAh = make_desc(sb);
            uint64_t dAl = make_desc(sb + TILE_BYTES);
            uint64_t dBh = make_desc(sb + 2 * TILE_BYTES);
            uint64_t dBl = make_desc(sb + 3 * TILE_BYTES);
            #pragma unroll
            for (int ks = 0; ks < 4; ks++)
                mma_f16_ss(tb, dAh + 2 * ks, dBh + 2 * ks, IDESC_128,
                           (c > 0 || ks > 0) ? 1u : 0u);
            #pragma unroll
            for (int ks = 0; ks < 4; ks++)
                mma_f16_ss(tb, dAh + 2 * ks, dBl + 2 * ks, IDESC_128, 1u);
            #pragma unroll
            for (int ks = 0; ks < 4; ks++)
                mma_f16_ss(tb, dAl + 2 * ks, dBh + 2 * ks, IDESC_128, 1u);
            asm volatile(
                "tcgen05.commit.cta_group::1.mbarrier::arrive::one.shared::cluster.b64 [%0];"
                :: "r"(smem_u32(&s_mbar[s])) : "memory");
        }
        if (c + NSTAGES < NC) {
            MBARRIER_WAIT_PARITY(smem_u32(&s_mbar[s]), (uint32_t)((c / NSTAGES) & 1));
            load_chunk(dynbase + s * STAGE_BYTES, Ah, Al, Bh, Bl, m0, n0, K,
                       (c + NSTAGES) * 64, tid);
        }
        asm volatile("cp.async.commit_group;" ::: "memory");
    }
    {
        int slast = (NC - 1) % NSTAGES;
        MBARRIER_WAIT_PARITY(smem_u32(&s_mbar[slast]),
                             (uint32_t)(((NC - 1) / NSTAGES) & 1));
    }
    asm volatile("tcgen05.fence::after_thread_sync;" ::: "memory");

    const int sub = wid & 3;
    const int half = wid >> 2;
    float lmax = 0.0f;
    float* crow = C + (size_t)(m0 + sub * 32 + lid) * N + n0 + half * 64;
    #pragma unroll
    for (int g = 0; g < 2; g++) {
        uint32_t r[32];
        TCGEN05_LD_X32(r, tb + half * 64 + g * 32);
        asm volatile("tcgen05.wait::ld.sync.aligned;" ::: "memory");
        #pragma unroll
        for (int q = 0; q < 8; q++) {
            float4 v = make_float4(__uint_as_float(r[q * 4 + 0]),
                                   __uint_as_float(r[q * 4 + 1]),
                                   __uint_as_float(r[q * 4 + 2]),
                                   __uint_as_float(r[q * 4 + 3]));
            *(float4*)(crow + g * 32 + q * 4) = v;
            lmax = fmaxf(lmax, fmaxf(fmaxf(fabsf(v.x), fabsf(v.y)),
                                     fmaxf(fabsf(v.z), fabsf(v.w))));
        }
    }
    asm volatile("tcgen05.fence::before_thread_sync;" ::: "memory");
    if (amax_slot) {
        #pragma unroll
        for (int o = 16; o; o >>= 1)
            lmax = fmaxf(lmax, __shfl_xor_sync(0xffffffffu, lmax, o));
        if (lid == 0) s_red[wid] = lmax;
    }
    __syncthreads();
    if (amax_slot && tid == 0) {
        float m = s_red[0];
        #pragma unroll
        for (int i = 1; i < 8; i++) m = fmaxf(m, s_red[i]);
        atomicMax(amax_slot, __float_as_uint(m));
    }
    if (wid == 0) {
        asm volatile("tcgen05.dealloc.cta_group::1.sync.aligned.b32 %0, %1;"
                     :: "r"(tb), "r"(128u));
    }

#else  // ===================== mma.sync fallback ============================
    // warp grid: 4 (m) x 2 (n); warp tile 32x64
    const int m0w = (wid & 3) * 32;
    const int n0w = (wid >> 2) * 64;
    float acc[2][8][4];
    #pragma unroll
    for (int i = 0; i < 2; i++)
        #pragma unroll
        for (int j = 0; j < 8; j++)
            #pragma unroll
            for (int q = 0; q < 4; q++) acc[i][j][q] = 0.0f;

    const int g  = lid >> 3;          // ldmatrix group 0..3
    const int lr = lid & 7;
    const int rsel = (g & 1) * 8 + lr;   // row-within-16 for this lane
    const int csel = (g >> 1) * 16;      // byte-col offset 0 / 16

    #pragma unroll
    for (int c = 0; c < NSTAGES; c++) {
        load_chunk(dynbase + c * STAGE_BYTES, Ah, Al, Bh, Bl, m0, n0, K, c * 64, tid);
        asm volatile("cp.async.commit_group;" ::: "memory");
    }

    for (int c = 0; c < NC; ++c) {
        int s = c - (c / NSTAGES) * NSTAGES;
        asm volatile("cp.async.wait_group %0;" :: "n"(NSTAGES - 1) : "memory");
        __syncthreads();
        uint32_t sb = dynbase + s * STAGE_BYTES;
        uint32_t aH = sb, aL = sb + TILE_BYTES;
        uint32_t bH = sb + 2 * TILE_BYTES, bL = sb + 3 * TILE_BYTES;

        #pragma unroll
        for (int ks = 0; ks < 4; ks++) {
            const int cb = ks * 32 + csel;
            uint32_t ah[2][4], al[2][4];
            #pragma unroll
            for (int mt = 0; mt < 2; mt++) {
                uint32_t off = (uint32_t)((m0w + mt * 16 + rsel) * 128 + cb);
                uint32_t sw = off ^ ((off >> 3) & 0x70);
                ldsm_x4(aH + sw, ah[mt]);
                ldsm_x4(aL + sw, al[mt]);
            }
            #pragma unroll
            for (int np = 0; np < 4; np++) {
                uint32_t off = (uint32_t)((n0w + np * 16 + rsel) * 128 + cb);
                uint32_t sw = off ^ ((off >> 3) & 0x70);
                uint32_t bh[4], bl[4];
                ldsm_x4(bH + sw, bh);
                ldsm_x4(bL + sw, bl);
                #pragma unroll
                for (int mt = 0; mt < 2; mt++) {
                    mma16816(acc[mt][np * 2 + 0], ah[mt], bh[0], bh[2]);
                    mma16816(acc[mt][np * 2 + 1], ah[mt], bh[1], bh[3]);
                    mma16816(acc[mt][np * 2 + 0], ah[mt], bl[0], bl[2]);
                    mma16816(acc[mt][np * 2 + 1], ah[mt], bl[1], bl[3]);
                    mma16816(acc[mt][np * 2 + 0], al[mt], bh[0], bh[2]);
                    mma16816(acc[mt][np * 2 + 1], al[mt], bh[1], bh[3]);
                }
            }
        }
        __syncthreads();
        if (c + NSTAGES < NC) {
            load_chunk(dynbase + s * STAGE_BYTES, Ah, Al, Bh, Bl, m0, n0, K,
                       (c + NSTAGES) * 64, tid);
        }
        asm volatile("cp.async.commit_group;" ::: "memory");
    }

    // epilogue
    const int gq = lid >> 2, q4 = lid & 3;
    float lmax = 0.0f;
    #pragma unroll
    for (int mt = 0; mt < 2; mt++) {
        #pragma unroll
        for (int nt = 0; nt < 8; nt++) {
            float* cp0 = C + (size_t)(m0 + m0w + mt * 16 + gq) * N
                           + n0 + n0w + nt * 8 + q4 * 2;
            float* cp1 = cp0 + 8 * (size_t)N;
            cp0[0] = acc[mt][nt][0]; cp0[1] = acc[mt][nt][1];
            cp1[0] = acc[mt][nt][2]; cp1[1] = acc[mt][nt][3];
            #pragma unroll
            for (int q = 0; q < 4; q++)
                lmax = fmaxf(lmax, fabsf(acc[mt][nt][q]));
        }
    }
    if (amax_slot) {
        #pragma unroll
        for (int o = 16; o; o >>= 1)
            lmax = fmaxf(lmax, __shfl_xor_sync(0xffffffffu, lmax, o));
        if (lid == 0) s_red[wid] = lmax;
        __syncthreads();
        if (tid == 0) {
            float m = s_red[0];
            #pragma unroll
            for (int i = 1; i < 8; i++) m = fmaxf(m, s_red[i]);
            atomicMax(amax_slot, __float_as_uint(m));
        }
    }
#endif
}

// ---------------------------------------------------------------------------
// Elementwise kernels
// ---------------------------------------------------------------------------
__global__ void k_zero_amax() {
    if (threadIdx.x < 8) g_amax[threadIdx.x] = 0u;
}

__global__ void k_amax(const float4* __restrict__ p, size_t n4, int slot) {
    float m = 0.0f;
    for (size_t i = (size_t)blockIdx.x * blockDim.x + threadIdx.x; i < n4;
         i += (size_t)gridDim.x * blockDim.x) {
        float4 v = p[i];
        m = fmaxf(m, fmaxf(fmaxf(fabsf(v.x), fabsf(v.y)),
                           fmaxf(fabsf(v.z), fabsf(v.w))));
    }
    #pragma unroll
    for (int o = 16; o; o >>= 1) m = fmaxf(m, __shfl_xor_sync(0xffffffffu, m, o));
    __shared__ float red[32];
    int wid = threadIdx.x >> 5, lid = threadIdx.x & 31;
    if (lid == 0) red[wid] = m;
    __syncthreads();
    if (threadIdx.x == 0) {
        int nw = (blockDim.x + 31) >> 5;
        float mm = red[0];
        for (int i = 1; i < nw; i++) mm = fmaxf(mm, red[i]);
        atomicMax(&g_amax[slot], __float_as_uint(mm));
    }
}

__global__ void k_quant_split(const float4* __restrict__ in,
                              __nv_bfloat162* __restrict__ h,
                              __nv_bfloat162* __restrict__ l,
                              size_t n4, int slot) {
    float s = scale16(__uint_as_float(g_amax[slot]));
    for (size_t i = (size_t)blockIdx.x * blockDim.x + threadIdx.x; i < n4;
         i += (size_t)gridDim.x * blockDim.x) {
        float4 v = in[i];
        float q[4] = {qdq16(v.x, s), qdq16(v.y, s), qdq16(v.z, s), qdq16(v.w, s)};
        __nv_bfloat16 hh[4], ll[4];
        #pragma unroll
        for (int c = 0; c < 4; c++) {
            hh[c] = __float2bfloat16(q[c]);
            ll[c] = __float2bfloat16(q[c] - __bfloat162float(hh[c]));
        }
        h[2 * i]     = __halves2bfloat162(hh[0], hh[1]);
        h[2 * i + 1] = __halves2bfloat162(hh[2], hh[3]);
        l[2 * i]     = __halves2bfloat162(ll[0], ll[1]);
        l[2 * i + 1] = __halves2bfloat162(ll[2], ll[3]);
    }
}

__global__ void k_dequant_w_split(const float* __restrict__ w,
                                  __nv_bfloat16* __restrict__ oh,
                                  __nv_bfloat16* __restrict__ ol, int nblocks) {
    int warp = (blockIdx.x * blockDim.x + threadIdx.x) >> 5;
    int lane = threadIdx.x & 31;
    if (warp >= nblocks) return;
    size_t base = (size_t)warp * 32;
    float v = w[base + lane];
    float a = fabsf(v);
    #pragma unroll
    for (int off = 16; off; off >>= 1)
        a = fmaxf(a, __shfl_xor_sync(0xffffffffu, a, off));
    float s = fmaxf(__fdiv_rn(a, 7.0f), 1e-12f);
    float q = rintf(__fdiv_rn(v, s));
    q = fminf(fmaxf(q, -8.0f), 7.0f);
    float wd = q * s;
    __nv_bfloat16 hi = __float2bfloat16(wd);
    __nv_bfloat16 lo = __float2bfloat16(wd - __bfloat162float(hi));
    oh[base + lane] = hi;
    ol[base + lane] = lo;
}

__global__ void k_silu(float4* __restrict__ gate, size_t n4) {
    float sg = scale16(__uint_as_float(g_amax[2]));
    float m = 0.0f;
    for (size_t i = (size_t)blockIdx.x * blockDim.x + threadIdx.x; i < n4;
         i += (size_t)gridDim.x * blockDim.x) {
        float4 v = gate[i];
        float r[4] = {v.x, v.y, v.z, v.w};
        #pragma unroll
        for (int c = 0; c < 4; c++) {
            float g1 = qdq16(r[c], sg);
            float sig = __fdiv_rn(1.0f, 1.0f + expf(-g1));
            sig = fminf(fmaxf(rintf(sig * 65536.0f), 0.0f), 65535.0f) * (1.0f / 65536.0f);
            float t = g1 * sig;
            r[c] = t;
            m = fmaxf(m, fabsf(t));
        }
        gate[i] = make_float4(r[0], r[1], r[2], r[3]);
    }
    #pragma unroll
    for (int o = 16; o; o >>= 1) m = fmaxf(m, __shfl_xor_sync(0xffffffffu, m, o));
    __shared__ float red[32];
    int wid = threadIdx.x >> 5, lid = threadIdx.x & 31;
    if (lid == 0) red[wid] = m;
    __syncthreads();
    if (threadIdx.x == 0) {
        int nw = (blockDim.x + 31) >> 5;
        float mm = red[0];
        for (int i = 1; i < nw; i++) mm = fmaxf(mm, red[i]);
        atomicMax(&g_amax[3], __float_as_uint(mm));
    }
}

__global__ void k_mul(const float4* __restrict__ t, float4* __restrict__ up, size_t n4) {
    float st = scale16(__uint_as_float(g_amax[3]));
    float su = scale16(__uint_as_float(g_amax[1]));
    float m = 0.0f;
    for (size_t i = (size_t)blockIdx.x * blockDim.x + threadIdx.x; i < n4;
         i += (size_t)gridDim.x * blockDim.x) {
        float4 tv = t[i];
        float4 uv = up[i];
        float rt[4] = {tv.x, tv.y, tv.z, tv.w};
        float ru[4] = {uv.x, uv.y, uv.z, uv.w};
        #pragma unroll
        for (int c = 0; c < 4; c++) {
            float g2 = qdq16(rt[c], st);
            float u  = qdq16(ru[c], su);
            float p  = g2 * u;
            ru[c] = p;
            m = fmaxf(m, fabsf(p));
        }
        up[i] = make_float4(ru[0], ru[1], ru[2], ru[3]);
    }
    #pragma unroll
    for (int o = 16; o; o >>= 1) m = fmaxf(m, __shfl_xor_sync(0xffffffffu, m, o));
    __shared__ float red[32];
    int wid = threadIdx.x >> 5, lid = threadIdx.x & 31;
    if (lid == 0) red[wid] = m;
    __syncthreads();
    if (threadIdx.x == 0) {
        int nw = (blockDim.x + 31) >> 5;
        float mm = red[0];
        for (int i = 1; i < nw; i++) mm = fmaxf(mm, red[i]);
        atomicMax(&g_amax[4], __float_as_uint(mm));
    }
}

// ---------------------------------------------------------------------------
// Host launch
// ---------------------------------------------------------------------------
extern "C" void kernel_launch(void* const* d_in, const int* in_sizes, int n_in,
                              void* d_out, int out_size)
{
    const float* x  = (const float*)d_in[0];
    const float* wg = (const float*)d_in[1];
    const float* wu = (const float*)d_in[2];
    const float* wd = (const float*)d_in[3];
    float* out = (float*)d_out;

    __nv_bfloat16 *p_xh, *p_xl, *p_wuh, *p_wul, *p_wgh, *p_wgl, *p_wdh, *p_wdl, *p_ph, *p_pl;
    float *p_up, *p_gate;
    unsigned int* p_amax;
    cudaGetSymbolAddress((void**)&p_xh,  g_xh);
    cudaGetSymbolAddress((void**)&p_xl,  g_xl);
    cudaGetSymbolAddress((void**)&p_wuh, g_wuh);
    cudaGetSymbolAddress((void**)&p_wul, g_wul);
    cudaGetSymbolAddress((void**)&p_wgh, g_wgh);
    cudaGetSymbolAddress((void**)&p_wgl, g_wgl);
    cudaGetSymbolAddress((void**)&p_wdh, g_wdh);
    cudaGetSymbolAddress((void**)&p_wdl, g_wdl);
    cudaGetSymbolAddress((void**)&p_ph,  g_ph);
    cudaGetSymbolAddress((void**)&p_pl,  g_pl);
    cudaGetSymbolAddress((void**)&p_up,  g_up);
    cudaGetSymbolAddress((void**)&p_gate, g_gate);
    cudaGetSymbolAddress((void**)&p_amax, g_amax);

    cudaFuncSetAttribute(gemm_bf16_split,
                         cudaFuncAttributeMaxDynamicSharedMemorySize, GEMM_DYN_SMEM);

    const size_t nx4 = (size_t)M_TOK * H_DIM / 4;
    const size_t ni4 = (size_t)M_TOK * I_DIM / 4;

    k_zero_amax<<<1, 8>>>();

    k_amax<<<2048, 256>>>((const float4*)x, nx4, 0);
    k_quant_split<<<2048, 256>>>((const float4*)x, (__nv_bfloat162*)p_xh,
                                 (__nv_bfloat162*)p_xl, nx4, 0);
    {
        int nb = (I_DIM * H_DIM) / 32;
        int cta = (nb * 32 + 255) / 256;
        k_dequant_w_split<<<cta, 256>>>(wu, p_wuh, p_wul, nb);
        k_dequant_w_split<<<cta, 256>>>(wg, p_wgh, p_wgl, nb);
        k_dequant_w_split<<<cta, 256>>>(wd, p_wdh, p_wdl, nb);
    }
    {
        dim3 grid(I_DIM / 128, M_TOK / 128);
        gemm_bf16_split<<<grid, 256, GEMM_DYN_SMEM>>>(
            p_xh, p_xl, p_wuh, p_wul, p_up, I_DIM, H_DIM, p_amax + 1);
        gemm_bf16_split<<<grid, 256, GEMM_DYN_SMEM>>>(
            p_xh, p_xl, p_wgh, p_wgl, p_gate, I_DIM, H_DIM, p_amax + 2);
    }
    k_silu<<<4096, 256>>>((float4*)p_gate, ni4);
    k_mul<<<4096, 256>>>((const float4*)p_gate, (float4*)p_up, ni4);
    k_quant_split<<<4096, 256>>>((const float4*)p_up, (__nv_bfloat162*)p_ph,
                                 (__nv_bfloat162*)p_pl, ni4, 4);
    {
        dim3 grid(H_DIM / 128, M_TOK / 128);
        gemm_bf16_split<<<grid, 256, GEMM_DYN_SMEM>>>(
            p_ph, p_pl, p_wdh, p_wdl, out, H_DIM, I_DIM, nullptr);
    }
}